// round 3
// baseline (speedup 1.0000x reference)
#include <cuda_runtime.h>
#include <math.h>

// Problem constants (fixed by reference setup_inputs)
#define BB    512
#define KK    8
#define PP    6
#define DD    1024
#define NIDS  64
#define MARGIN 0.2f

// Scratch (no allocations allowed): center SUMS [2][NIDS][PP][DD]
__device__ float g_center[2 * NIDS * PP * DD];   // 786432 floats = 3 MB
__device__ float g_w[BB];                        // fused per-sample weight
__device__ float g_cinv[BB];                     // 1/max(cnt_cross,1) for sample b
__device__ int   g_cbase[BB];                    // cross-center base element offset

// ---------------------------------------------------------------------------
// K0: zero the center-sum scratch (float4 stores)
// ---------------------------------------------------------------------------
__global__ void k0_zero() {
    int i = blockIdx.x * blockDim.x + threadIdx.x;      // float4 index
    const int n4 = (2 * NIDS * PP * DD) / 4;            // 196608
    if (i < n4) {
        float4 z = make_float4(0.f, 0.f, 0.f, 0.f);
        reinterpret_cast<float4*>(g_center)[i] = z;
    }
}

// ---------------------------------------------------------------------------
// K1: one block, 512 threads. Counts, validity, id_count, fused weights,
//     cross-center inverse counts + base offsets, zero d_out.
// ---------------------------------------------------------------------------
__global__ void k1_setup(const int* __restrict__ pids,
                         const int* __restrict__ camids,
                         float* __restrict__ out) {
    __shared__ int   scnt[2 * NIDS];     // [mod][id], mod 0 = rgb, 1 = sar
    __shared__ int   svalid[NIDS];
    __shared__ int   s_idcount;

    int t = threadIdx.x;
    if (t < 2 * NIDS) scnt[t] = 0;
    if (t == 0) s_idcount = 0;
    __syncthreads();

    int pid = 0, cam = 0;
    if (t < BB) {
        pid = pids[t];
        cam = camids[t];
        int mod = (cam == 0) ? 0 : 1;                    // own modality
        atomicAdd(&scnt[mod * NIDS + pid], 1);
    }
    __syncthreads();

    if (t < NIDS) {
        int v = (scnt[t] > 0 && scnt[NIDS + t] > 0) ? 1 : 0;
        svalid[t] = v;
        if (v) atomicAdd(&s_idcount, 1);
    }
    __syncthreads();

    float denom = fmaxf((float)s_idcount, 1.0f);

    if (t < BB) {
        int rgb = (cam == 0);
        int own_mod   = rgb ? 0 : 1;
        int cross_mod = rgb ? 1 : 0;                     // rgb pulls toward sar center
        float grp = fmaxf((float)scnt[own_mod * NIDS + pid], 1.0f);
        float w = svalid[pid] ? (1.0f / (grp * (float)KK * (float)PP * denom)) : 0.0f;
        g_w[t] = w;
        g_cinv[t] = 1.0f / fmaxf((float)scnt[cross_mod * NIDS + pid], 1.0f);
        g_cbase[t] = (cross_mod * NIDS + pid) * PP * DD;
    }
    if (t == 0) out[0] = 0.0f;
}

// ---------------------------------------------------------------------------
// K2: segment-sum f_original into g_center[mod][pid] via float atomics.
//     One thread per float4 of f_original.
// ---------------------------------------------------------------------------
__global__ void k2_sums(const float* __restrict__ f_orig,
                        const int* __restrict__ pids,
                        const int* __restrict__ camids) {
    int i = blockIdx.x * blockDim.x + threadIdx.x;      // float4 index
    const int row4 = (PP * DD) / 4;                     // 1536 float4 per sample
    const int n4 = BB * row4;
    if (i >= n4) return;
    int b = i / row4;
    int r = i - b * row4;                               // float4 within [P,D]
    int pid = pids[b];
    int mod = (camids[b] == 0) ? 0 : 1;
    float4 v = reinterpret_cast<const float4*>(f_orig)[i];
    float* dst = g_center + (mod * NIDS + pid) * PP * DD + r * 4;
    atomicAdd(dst + 0, v.x);
    atomicAdd(dst + 1, v.y);
    atomicAdd(dst + 2, v.z);
    atomicAdd(dst + 3, v.w);
}

// ---------------------------------------------------------------------------
// K4: main reduction. One warp per (b,k,p) row of length D=1024.
//     Normalizes center sums on the fly (c = s * inv_cnt).
//     8 warps per block, 3072 blocks. Accumulates hinge*w into out[0].
// ---------------------------------------------------------------------------
__global__ void __launch_bounds__(256) k4_main(const float* __restrict__ f_orig,
                                               const float* __restrict__ f_gen,
                                               float* __restrict__ out) {
    __shared__ float spart[8];

    int warp = threadIdx.x >> 5;
    int lane = threadIdx.x & 31;
    int row = blockIdx.x * 8 + warp;                    // 0 .. B*K*P-1
    // row -> (b, k, p)
    int b = row / (KK * PP);
    int rem = row - b * (KK * PP);
    int k = rem / PP;
    int p = rem - k * PP;

    const float* gp = f_gen + ((size_t)((b * KK + k) * PP + p)) * DD;
    const float* op = f_orig + ((size_t)(b * PP + p)) * DD;
    const float* cp = g_center + g_cbase[b] + p * DD;
    const float cinv = g_cinv[b];

    float s_pull = 0.0f, s_push = 0.0f;
#pragma unroll
    for (int it = 0; it < 8; ++it) {
        int d = it * 128 + lane * 4;
        float4 g = *reinterpret_cast<const float4*>(gp + d);
        float4 c = *reinterpret_cast<const float4*>(cp + d);
        float4 o = *reinterpret_cast<const float4*>(op + d);
        float dx, dy, dz, dw;
        dx = g.x - c.x * cinv; dy = g.y - c.y * cinv;
        dz = g.z - c.z * cinv; dw = g.w - c.w * cinv;
        s_pull += dx * dx + dy * dy + dz * dz + dw * dw;
        dx = g.x - o.x; dy = g.y - o.y; dz = g.z - o.z; dw = g.w - o.w;
        s_push += dx * dx + dy * dy + dz * dz + dw * dw;
    }
#pragma unroll
    for (int off = 16; off; off >>= 1) {
        s_pull += __shfl_down_sync(0xffffffffu, s_pull, off);
        s_push += __shfl_down_sync(0xffffffffu, s_push, off);
    }
    if (lane == 0) {
        float h = sqrtf(s_pull) - sqrtf(s_push) + MARGIN;
        h = fmaxf(h, 0.0f) * g_w[b];
        spart[warp] = h;
    }
    __syncthreads();
    if (threadIdx.x == 0) {
        float s = 0.0f;
#pragma unroll
        for (int i = 0; i < 8; ++i) s += spart[i];
        atomicAdd(out, s);
    }
}

// ---------------------------------------------------------------------------
extern "C" void kernel_launch(void* const* d_in, const int* in_sizes, int n_in,
                              void* d_out, int out_size) {
    const float* f_orig = (const float*)d_in[0];
    const float* f_gen  = (const float*)d_in[1];
    const int*   pids   = (const int*)d_in[2];
    const int*   camids = (const int*)d_in[3];
    float*       out    = (float*)d_out;

    // K0: zero center scratch — 196608 float4s
    k0_zero<<<(196608 + 255) / 256, 256>>>();
    // K1: setup (one block)
    k1_setup<<<1, 512>>>(pids, camids, out);
    // K2: segment sums — B*P*D/4 = 786432 threads
    k2_sums<<<(786432 + 255) / 256, 256>>>(f_orig, pids, camids);
    // K4: main — B*K*P = 24576 rows, 8 warps/block
    k4_main<<<24576 / 8, 256>>>(f_orig, f_gen, out);
}

// round 4
// speedup vs baseline: 1.2916x; 1.2916x over previous
#include <cuda_runtime.h>
#include <math.h>

// Problem constants (fixed by reference setup_inputs)
#define BB    512
#define KK    8
#define PP    6
#define DD    1024
#define NIDS  64
#define NGRP  (2 * NIDS)          // (mod, id) groups
#define MARGIN 0.2f

// Scratch (no allocations allowed)
__device__ float g_w[BB];         // fused per-sample weight (includes 1/(grp*K*P*denom))
__device__ float g_cinv[BB];      // 1/max(cnt_cross,1)
__device__ int   g_cgrp[BB];      // cross-modality group index for sample b
__device__ int   g_off[NGRP + 1]; // CSR offsets per group
__device__ int   g_list[BB];      // CSR sample indices grouped by (mod,id)

// ---------------------------------------------------------------------------
// K1: one block, 512 threads. Counts, validity, id_count, fused weights,
//     CSR group lists, zero d_out.
// ---------------------------------------------------------------------------
__global__ void k1_setup(const int* __restrict__ pids,
                         const int* __restrict__ camids,
                         float* __restrict__ out) {
    __shared__ int scnt[NGRP];        // [mod][id], mod 0 = rgb, 1 = sar
    __shared__ int scur[NGRP];
    __shared__ int soff[NGRP + 1];
    __shared__ int svalid[NIDS];
    __shared__ int s_idcount;

    int t = threadIdx.x;
    if (t < NGRP) { scnt[t] = 0; scur[t] = 0; }
    if (t == 0) s_idcount = 0;
    __syncthreads();

    int pid = 0, cam = 0, own_grp = 0;
    if (t < BB) {
        pid = pids[t];
        cam = camids[t];
        int mod = (cam == 0) ? 0 : 1;              // own modality
        own_grp = mod * NIDS + pid;
        atomicAdd(&scnt[own_grp], 1);
    }
    __syncthreads();

    if (t < NIDS) {
        int v = (scnt[t] > 0 && scnt[NIDS + t] > 0) ? 1 : 0;
        svalid[t] = v;
        if (v) atomicAdd(&s_idcount, 1);
    }
    __syncthreads();

    if (t == 0) {                                  // serial prefix over 128 groups
        int acc = 0;
        for (int g = 0; g < NGRP; ++g) { soff[g] = acc; acc += scnt[g]; }
        soff[NGRP] = acc;
    }
    __syncthreads();

    if (t <= NGRP) g_off[t] = soff[t];

    float denom = fmaxf((float)s_idcount, 1.0f);

    if (t < BB) {
        int rgb = (cam == 0);
        int cross_grp = (rgb ? 1 : 0) * NIDS + pid;
        float grp_cnt = fmaxf((float)scnt[own_grp], 1.0f);
        float w = svalid[pid] ? (1.0f / (grp_cnt * (float)KK * (float)PP * denom)) : 0.0f;
        g_w[t] = w;
        g_cinv[t] = 1.0f / fmaxf((float)scnt[cross_grp], 1.0f);
        g_cgrp[t] = cross_grp;
        int pos = atomicAdd(&scur[own_grp], 1);
        g_list[soff[own_grp] + pos] = t;
    }
    if (t == 0) out[0] = 0.0f;
}

// ---------------------------------------------------------------------------
// K4: one block per (b,p). Builds cross-center row in SMEM (gather over CSR
//     group members), stages own f_original row in SMEM, then 8 warps each
//     stream one k-row of f_generated (batched float4 loads) against SMEM.
// ---------------------------------------------------------------------------
__global__ void __launch_bounds__(256) k4_main(const float* __restrict__ f_orig,
                                               const float* __restrict__ f_gen,
                                               float* __restrict__ out) {
    __shared__ float so[DD];          // own f_original row
    __shared__ float sc[DD];          // cross-modality center row
    __shared__ float spart[8];

    int bp = blockIdx.x;              // 0 .. B*P-1
    int b = bp / PP;
    int p = bp - b * PP;
    int t = threadIdx.x;              // 256 threads; thread t owns float4 #t (DD/4 == 256)

    const float4* fo4 = reinterpret_cast<const float4*>(f_orig);

    // Stage own row
    size_t own_row4 = ((size_t)(b * PP + p) * DD) >> 2;
    float4 o4 = fo4[own_row4 + t];
    reinterpret_cast<float4*>(so)[t] = o4;

    // Gather cross-center row: sum member rows, scale by 1/cnt
    int grp = g_cgrp[b];
    int off = g_off[grp];
    int end = g_off[grp + 1];
    float cinv = g_cinv[b];
    float4 acc = make_float4(0.f, 0.f, 0.f, 0.f);
    for (int j = off; j < end; ++j) {
        int bs = g_list[j];
        float4 v = fo4[(((size_t)(bs * PP + p) * DD) >> 2) + t];
        acc.x += v.x; acc.y += v.y; acc.z += v.z; acc.w += v.w;
    }
    acc.x *= cinv; acc.y *= cinv; acc.z *= cinv; acc.w *= cinv;
    reinterpret_cast<float4*>(sc)[t] = acc;
    __syncthreads();

    // Main stream: warp k handles f_generated[b, k, p, :]
    int k = t >> 5;
    int lane = t & 31;
    const float4* gp = reinterpret_cast<const float4*>(
        f_gen + ((size_t)((b * KK + k) * PP + p)) * DD);

    float4 g[8];
#pragma unroll
    for (int it = 0; it < 8; ++it) g[it] = gp[it * 32 + lane];

    float s_pull = 0.0f, s_push = 0.0f;
#pragma unroll
    for (int it = 0; it < 8; ++it) {
        float4 o = reinterpret_cast<const float4*>(so)[it * 32 + lane];
        float4 c = reinterpret_cast<const float4*>(sc)[it * 32 + lane];
        float dx, dy, dz, dw;
        dx = g[it].x - c.x; dy = g[it].y - c.y;
        dz = g[it].z - c.z; dw = g[it].w - c.w;
        s_pull += dx * dx + dy * dy + dz * dz + dw * dw;
        dx = g[it].x - o.x; dy = g[it].y - o.y;
        dz = g[it].z - o.z; dw = g[it].w - o.w;
        s_push += dx * dx + dy * dy + dz * dz + dw * dw;
    }
#pragma unroll
    for (int off2 = 16; off2; off2 >>= 1) {
        s_pull += __shfl_down_sync(0xffffffffu, s_pull, off2);
        s_push += __shfl_down_sync(0xffffffffu, s_push, off2);
    }
    if (lane == 0) {
        float h = sqrtf(s_pull) - sqrtf(s_push) + MARGIN;
        spart[k] = fmaxf(h, 0.0f) * g_w[b];
    }
    __syncthreads();
    if (t == 0) {
        float s = 0.0f;
#pragma unroll
        for (int i = 0; i < 8; ++i) s += spart[i];
        atomicAdd(out, s);
    }
}

// ---------------------------------------------------------------------------
extern "C" void kernel_launch(void* const* d_in, const int* in_sizes, int n_in,
                              void* d_out, int out_size) {
    const float* f_orig = (const float*)d_in[0];
    const float* f_gen  = (const float*)d_in[1];
    const int*   pids   = (const int*)d_in[2];
    const int*   camids = (const int*)d_in[3];
    float*       out    = (float*)d_out;

    k1_setup<<<1, 512>>>(pids, camids, out);
    k4_main<<<BB * PP, 256>>>(f_orig, f_gen, out);
}